// round 6
// baseline (speedup 1.0000x reference)
#include <cuda_runtime.h>

#define B 16
#define T 512
#define D 256
#define HS 512
#define DA 64
#define R 8
#define G4 2048
#define NCTA 128
#define SCAN_THREADS 512
#define TC 64
#define NCH (T/TC)   // 8

// -------- scratch (static device arrays: allocation-free) --------
__device__ float g_s [B*T*R];
__device__ float g_e [B*T*R];
__device__ float g_iz[B*T*R];
__device__ float g_S [B*NCH*R*D];                // per-chunk e*x sums, 1 MB
__device__ float g_M [B*T*D];
__device__ float g_gates[(size_t)B*T*G4];        // 64 MB
__device__ float g_hbuf[2][HS*B];                // [h][b] transposed, double-buffered
__device__ unsigned g_arrive[NCTA*32];           // barrier slots, 128B stride

typedef unsigned long long ull;

// ---- packed f32x2 helpers (Blackwell: 2 MACs / inst) ----
__device__ __forceinline__ void ffma2(ull& d, ull a, ull b){
    asm("fma.rn.f32x2 %0, %1, %2, %0;" : "+l"(d) : "l"(a), "l"(b));
}
__device__ __forceinline__ ull addf2(ull a, ull b){
    ull d; asm("add.rn.f32x2 %0, %1, %2;" : "=l"(d) : "l"(a), "l"(b)); return d;
}
__device__ __forceinline__ ull pack2(float x){
    ull r; asm("mov.b64 %0, {%1, %1};" : "=l"(r) : "r"(__float_as_uint(x))); return r;
}
__device__ __forceinline__ ull dbl2u(double d){ return (ull)__double_as_longlong(d); }
__device__ __forceinline__ float lo2(ull v){ return __uint_as_float((unsigned)v); }
__device__ __forceinline__ float hi2(ull v){ return __uint_as_float((unsigned)(v>>32)); }

__device__ __forceinline__ void st_release(unsigned* p, unsigned v){
    asm volatile("st.release.gpu.global.u32 [%0], %1;" :: "l"(p), "r"(v) : "memory");
}
__device__ __forceinline__ unsigned ld_acquire(const unsigned* p){
    unsigned v;
    asm volatile("ld.acquire.gpu.global.u32 %0, [%1];" : "=r"(v) : "l"(p) : "memory");
    return v;
}

// ---------------- init: reset barrier slots + h0 ----------------
__global__ void k_init() {
    int tid = threadIdx.x;
    for (int i = tid; i < 2*HS*B; i += blockDim.x)
        ((float*)g_hbuf)[i] = 0.f;
    for (int i = tid; i < NCTA*32; i += blockDim.x)
        g_arrive[i] = 0u;
}

// ------- s[b,t,r] = tanh(x@W1 + b1) @ W2 + b2  (8 rows / block) -------
__global__ void k_s(const float* __restrict__ x, const float* __restrict__ w1,
                    const float* __restrict__ b1, const float* __restrict__ w2,
                    const float* __restrict__ b2) {
    __shared__ float xs[8][D];
    __shared__ float h1[8][DA];
    int tid = threadIdx.x;                 // 256
    int row0 = blockIdx.x * 8;             // row = b*T + t
    for (int i = tid; i < 8*D; i += 256)
        xs[i/D][i%D] = x[(size_t)row0*D + i];
    __syncthreads();
    int a = tid & 63, rq = tid >> 6;
    float acc0 = b1[a], acc1 = b1[a];
    #pragma unroll 4
    for (int d = 0; d < D; d++) {
        float w = w1[d*DA + a];
        acc0 += xs[rq][d]   * w;
        acc1 += xs[rq+4][d] * w;
    }
    h1[rq][a]   = tanhf(acc0);
    h1[rq+4][a] = tanhf(acc1);
    __syncthreads();
    if (tid < 64) {
        int rr = tid >> 3, r = tid & 7;
        float acc = b2[r];
        #pragma unroll 8
        for (int a2 = 0; a2 < DA; a2++)
            acc += h1[rr][a2] * w2[a2*R + r];
        g_s[(size_t)(row0+rr)*R + r] = acc;
    }
}

// ------- running softmax denominators: e = exp(s), iz = 1/cumsum(e) -------
__global__ void k_cumsum() {
    int tid = threadIdx.x;
    if (tid >= B*R) return;
    int b = tid >> 3, r = tid & 7;
    const float* sp = &g_s [(size_t)b*T*R + r];
    float*       ep = &g_e [(size_t)b*T*R + r];
    float*       zp = &g_iz[(size_t)b*T*R + r];
    float z = 0.f;
    #pragma unroll 4
    for (int t = 0; t < T; t++) {
        float e = expf(sp[t*R]);
        z += e;
        ep[t*R] = e;
        zp[t*R] = 1.0f / z;
    }
}

// ------- pass 1: per-chunk sums S[b,ch,r,d] = sum_{j in chunk} e[j,r]*x[j,d] -------
__global__ void k_M1(const float* __restrict__ x) {
    __shared__ float es[TC*R];
    int b = blockIdx.x >> 3, ch = blockIdx.x & 7;
    int tid = threadIdx.x;                 // 256
    int t0 = ch*TC;
    for (int i = tid; i < TC*R; i += 256)
        es[i] = g_e[((size_t)b*T + t0)*R + i];
    __syncthreads();
    int d = tid;
    float acc[R] = {};
    const float* xp = &x[((size_t)b*T + t0)*D + d];
    #pragma unroll 4
    for (int j = 0; j < TC; j++) {
        float xv = xp[(size_t)j*D];
        #pragma unroll
        for (int r = 0; r < R; r++) acc[r] += es[j*R + r] * xv;
    }
    float* sp = &g_S[((size_t)(b*NCH + ch)*R)*D + d];
    #pragma unroll
    for (int r = 0; r < R; r++) sp[r*D] = acc[r];
}

// ------- pass 2: within-chunk weighted cumsum, seeded by chunk prefix -------
__global__ void k_M2(const float* __restrict__ x) {
    __shared__ float4 es[TC*2];
    __shared__ float4 zs[TC*2];
    int bi = blockIdx.x;
    int b = bi >> 4, dh = (bi >> 3) & 1, ch = bi & 7;
    int tid = threadIdx.x;                 // 128
    int t0 = ch*TC;
    const float4* eg = (const float4*)&g_e [((size_t)b*T + t0)*R];
    const float4* zg = (const float4*)&g_iz[((size_t)b*T + t0)*R];
    for (int i = tid; i < TC*2; i += 128) { es[i] = eg[i]; zs[i] = zg[i]; }
    __syncthreads();
    int d = dh*128 + tid;
    float4 clo = {0,0,0,0}, chi = {0,0,0,0};
    for (int c = 0; c < ch; c++) {
        const float* sp = &g_S[((size_t)(b*NCH + c)*R)*D + d];
        clo.x += sp[0];   clo.y += sp[D];   clo.z += sp[2*D]; clo.w += sp[3*D];
        chi.x += sp[4*D]; chi.y += sp[5*D]; chi.z += sp[6*D]; chi.w += sp[7*D];
    }
    const float* xp = &x[((size_t)b*T + t0)*D + d];
    float*       mp = &g_M[((size_t)b*T + t0)*D + d];
    for (int j = 0; j < TC; j += 4) {
        float xv[4];
        #pragma unroll
        for (int u = 0; u < 4; u++) xv[u] = xp[(size_t)(j+u)*D];
        float mo[4];
        #pragma unroll
        for (int u = 0; u < 4; u++) {
            float4 ea = es[2*(j+u)], eb = es[2*(j+u)+1];
            clo.x += ea.x*xv[u]; clo.y += ea.y*xv[u]; clo.z += ea.z*xv[u]; clo.w += ea.w*xv[u];
            chi.x += eb.x*xv[u]; chi.y += eb.y*xv[u]; chi.z += eb.z*xv[u]; chi.w += eb.w*xv[u];
            float4 za = zs[2*(j+u)], zb = zs[2*(j+u)+1];
            mo[u] = (clo.x*za.x + clo.y*za.y + clo.z*za.z + clo.w*za.w
                   + chi.x*zb.x + chi.y*zb.y + chi.z*zb.z + chi.w*zb.w) * 0.125f;
        }
        #pragma unroll
        for (int u = 0; u < 4; u++) mp[(size_t)(j+u)*D] = mo[u];
    }
}

// ------- gates = M(8192x256) @ W_i(256x2048) + bias, 128x128x16 / 8x8 tiles -------
#define GBM 128
#define GBN 128
#define GBK 16
__global__ void __launch_bounds__(256)
k_gemm(const float* __restrict__ Wi, const float* __restrict__ bias) {
    __shared__ float As[GBK][GBM+4];
    __shared__ float Bs[GBK][GBN+4];
    int tid = threadIdx.x;             // 256
    int tx = tid & 15, ty = tid >> 4;
    int rb = blockIdx.y * GBM, nb = blockIdx.x * GBN;
    ull c2[8][4] = {};
    for (int kb = 0; kb < D; kb += GBK) {
        #pragma unroll
        for (int j = 0; j < 2; j++) {
            int lin = tid + j*256;
            int m = lin >> 2, kq = (lin & 3)*4;
            float4 v = *(const float4*)&g_M[(size_t)(rb+m)*D + kb + kq];
            As[kq+0][m] = v.x; As[kq+1][m] = v.y;
            As[kq+2][m] = v.z; As[kq+3][m] = v.w;
        }
        #pragma unroll
        for (int j = 0; j < 2; j++) {
            int lin = tid + j*256;
            int kk2 = lin >> 5, nq = (lin & 31)*4;
            *(float4*)&Bs[kk2][nq] = *(const float4*)&Wi[(size_t)(kb+kk2)*G4 + nb + nq];
        }
        __syncthreads();
        #pragma unroll
        for (int kk = 0; kk < GBK; kk++) {
            float4 a0 = *(const float4*)&As[kk][ty*8];
            float4 a1 = *(const float4*)&As[kk][ty*8+4];
            double2 b0 = *(const double2*)&Bs[kk][tx*8];
            double2 b1 = *(const double2*)&Bs[kk][tx*8+4];
            ull bx0 = dbl2u(b0.x), bx1 = dbl2u(b0.y);
            ull bx2 = dbl2u(b1.x), bx3 = dbl2u(b1.y);
            float av[8] = {a0.x,a0.y,a0.z,a0.w,a1.x,a1.y,a1.z,a1.w};
            #pragma unroll
            for (int i = 0; i < 8; i++) {
                ull ap = pack2(av[i]);
                ffma2(c2[i][0], ap, bx0); ffma2(c2[i][1], ap, bx1);
                ffma2(c2[i][2], ap, bx2); ffma2(c2[i][3], ap, bx3);
            }
        }
        __syncthreads();
    }
    float4 bv0 = *(const float4*)&bias[nb + tx*8];
    float4 bv1 = *(const float4*)&bias[nb + tx*8 + 4];
    #pragma unroll
    for (int i = 0; i < 8; i++) {
        int row = rb + ty*8 + i;
        float4 o0 = make_float4(lo2(c2[i][0])+bv0.x, hi2(c2[i][0])+bv0.y,
                                lo2(c2[i][1])+bv0.z, hi2(c2[i][1])+bv0.w);
        float4 o1 = make_float4(lo2(c2[i][2])+bv1.x, hi2(c2[i][2])+bv1.y,
                                lo2(c2[i][3])+bv1.z, hi2(c2[i][3])+bv1.w);
        *(float4*)&g_gates[(size_t)row*G4 + nb + tx*8]     = o0;
        *(float4*)&g_gates[(size_t)row*G4 + nb + tx*8 + 4] = o1;
    }
}

// ------- persistent LSTM scan v5 -------
// CTA k owns h-indices [4k,4k+4). W stored in SMEM as PRE-DUPLICATED f32x2
// pairs (64 KB): the dot loop has ZERO pack2 MOVs -> per i: 2x LDS.128 (W),
// 1x LDS.128 (H), 8x FFMA2. Fusion done by warp 0 only (2 (b,j) combos per
// lane) with syncwarp + early lane-0 release (one less syncthreads on the
// critical path). gates_x prefetched one step ahead, issued before the poll.
// Grid barrier: per-CTA slots, hot-spin acquire polls (nanosleep only after
// 64 misses).
__global__ void __launch_bounds__(SCAN_THREADS, 1)
k_scan(const float* __restrict__ Whh, float* __restrict__ out) {
    extern __shared__ float sm[];
    float* Wd  = sm;                  // [512 h][16 c] duplicated pairs, 64 KB
    float* Hs  = sm + 16384;          // [512 h][16 b] 32 KB
    float* red = sm + 24576;          // [16 warps][16 c][20-pad b] 20 KB
    float* sg  = sm + 29696;          // [16 c][16 b]
    int tid = threadIdx.x;
    int k = blockIdx.x;
    int lane = tid & 31, warp = tid >> 5;
    int cx = lane & 3, by = (lane>>2)&3, ksub = lane>>4;
    int kbase = warp*32 + ksub;            // thread covers h = kbase + 2*i, i<16

    // stage duplicated W once: Wd[h][c] pair = {w, w},  c = gate*4 + j
    for (int idx = tid; idx < HS*16; idx += SCAN_THREADS) {
        int h = idx >> 4, c = idx & 15;
        float w = Whh[(size_t)h*G4 + (c>>2)*HS + k*4 + (c&3)];
        Wd[2*idx] = w; Wd[2*idx+1] = w;
    }
    __syncthreads();

    // fusion mapping (warp 0 only): lane l handles combos u=0,1:
    //   b = l>>1,  j = (l&1)*2 + u
    int fb = lane >> 1, fj0 = (lane & 1)*2;
    float creg0 = 0.f, creg1 = 0.f;
    float gxA[4], gxB[4];
    if (warp == 0) {
        const float* gp = &g_gates[((size_t)fb*T + 0)*G4 + k*4];
        #pragma unroll
        for (int g = 0; g < 4; g++) { gxA[g] = __ldg(gp + g*HS + fj0);
                                      gxB[g] = __ldg(gp + g*HS + fj0 + 1); }
    }

    float* hid_out = out;                         // (B,T,HS)
    float* ht_out  = out + (size_t)B*T*HS;        // (B,HS)
    float* ct_out  = ht_out + B*HS;               // (B,HS)

    for (int t = 0; t < T; t++) {
        // stage H into SMEM (32 KB, coalesced, L1-bypassing)
        {
            const float4* hb = (const float4*)&g_hbuf[t&1][0];
            float4* hs4 = (float4*)Hs;
            #pragma unroll
            for (int j = 0; j < 4; j++)
                hs4[tid + j*512] = __ldcv(hb + tid + j*512);
        }
        __syncthreads();

        // 4x4 outer-product dot, W pairs from SMEM (no MOV packing)
        ull acc[4][2] = {};
        #pragma unroll
        for (int i = 0; i < 16; i++) {
            int h = kbase + 2*i;
            const ull* wq = (const ull*)Wd + (h*16 + cx*4);
            ull w0 = wq[0], w1 = wq[1], w2 = wq[2], w3 = wq[3];
            double2 hd = *(const double2*)&Hs[h*16 + by*4];
            ull hx = dbl2u(hd.x), hy = dbl2u(hd.y);
            ffma2(acc[0][0], w0, hx); ffma2(acc[0][1], w0, hy);
            ffma2(acc[1][0], w1, hx); ffma2(acc[1][1], w1, hy);
            ffma2(acc[2][0], w2, hx); ffma2(acc[2][1], w2, hy);
            ffma2(acc[3][0], w3, hx); ffma2(acc[3][1], w3, hy);
        }
        // reduce ksub pairs via shfl (lanes xor 16 share (cx,by))
        #pragma unroll
        for (int q = 0; q < 4; q++) {
            acc[q][0] = addf2(acc[q][0], __shfl_xor_sync(0xffffffffu, acc[q][0], 16));
            acc[q][1] = addf2(acc[q][1], __shfl_xor_sync(0xffffffffu, acc[q][1], 16));
        }
        if (ksub == 0) {
            float* rp = &red[warp*320 + (cx*4)*20 + by*4];
            #pragma unroll
            for (int q = 0; q < 4; q++) {
                float4 v = make_float4(lo2(acc[q][0]), hi2(acc[q][0]),
                                       lo2(acc[q][1]), hi2(acc[q][1]));
                *(float4*)(rp + q*20) = v;
            }
        }
        __syncthreads();

        // reduce 16 warps: thread tid<256 owns (c = tid>>4, b = tid&15)
        if (tid < 256) {
            int c = tid >> 4, b = tid & 15;
            float s = 0.f;
            #pragma unroll
            for (int w = 0; w < 16; w++) s += red[w*320 + c*20 + b];
            sg[tid] = s;
        }
        __syncthreads();

        // gate fusion: warp 0 only, then early release via lane 0
        if (warp == 0) {
            #pragma unroll
            for (int u = 0; u < 2; u++) {
                int j = fj0 + u;
                float gx0 = u ? gxB[0] : gxA[0];
                float gx1 = u ? gxB[1] : gxA[1];
                float gx2 = u ? gxB[2] : gxA[2];
                float gx3 = u ? gxB[3] : gxA[3];
                float gi = sg[( 0 + j)*16 + fb] + gx0;
                float gf = sg[( 4 + j)*16 + fb] + gx1;
                float gg = sg[( 8 + j)*16 + fb] + gx2;
                float go = sg[(12 + j)*16 + fb] + gx3;
                float iv = 1.f/(1.f + __expf(-gi));
                float fv = 1.f/(1.f + __expf(-gf));
                float gv = tanhf(gg);
                float ov = 1.f/(1.f + __expf(-go));
                float& cr = u ? creg1 : creg0;
                cr = fv*cr + iv*gv;
                float hv = ov * tanhf(cr);
                int hj = k*4 + j;
                hid_out[((size_t)fb*T + t)*HS + hj] = hv;
                g_hbuf[(t+1)&1][hj*B + fb] = hv;     // transposed [h][b]
                if (t == T-1) { ht_out[fb*HS + hj] = hv; ct_out[fb*HS + hj] = cr; }
            }
            __syncwarp();                            // order h stores within warp 0
            if (lane == 0) st_release(&g_arrive[k*32], (unsigned)(t+1));
            // prefetch next step's gates_x (independent of h) while polling
            if (t+1 < T) {
                const float* gp = &g_gates[((size_t)fb*T + (t+1))*G4 + k*4];
                #pragma unroll
                for (int g = 0; g < 4; g++) { gxA[g] = __ldg(gp + g*HS + fj0);
                                              gxB[g] = __ldg(gp + g*HS + fj0 + 1); }
            }
        }

        // grid barrier: hot-spin acquire polls on per-CTA slots
        if (tid < NCTA) {
            const unsigned* slot = &g_arrive[tid*32];
            int spins = 0;
            while (ld_acquire(slot) < (unsigned)(t+1)) {
                if (++spins > 64) __nanosleep(20);
            }
        }
        __syncthreads();
    }
}

extern "C" void kernel_launch(void* const* d_in, const int* in_sizes, int n_in,
                              void* d_out, int out_size) {
    const float* x    = (const float*)d_in[0];
    const float* w1   = (const float*)d_in[1];
    const float* b1   = (const float*)d_in[2];
    const float* w2   = (const float*)d_in[3];
    const float* b2   = (const float*)d_in[4];
    const float* Wi   = (const float*)d_in[5];
    const float* Whh  = (const float*)d_in[6];
    const float* bias = (const float*)d_in[7];
    float* out = (float*)d_out;

    (void)in_sizes; (void)n_in; (void)out_size;

    k_init<<<1, 256>>>();
    k_s<<<(B*T)/8, 256>>>(x, w1, b1, w2, b2);
    k_cumsum<<<1, 128>>>();
    k_M1<<<B*NCH, 256>>>(x);
    k_M2<<<B*2*NCH, 128>>>(x);
    dim3 gg(G4/GBN, (B*T)/GBM);
    k_gemm<<<gg, 256>>>(Wi, bias);

    size_t smem = (size_t)(16384 + 8192 + 5120 + 256) * sizeof(float);  // 119,808 B
    cudaFuncSetAttribute(k_scan, cudaFuncAttributeMaxDynamicSharedMemorySize, (int)smem);
    k_scan<<<NCTA, SCAN_THREADS, smem>>>(Whh, out);
}

// round 7
// speedup vs baseline: 1.0170x; 1.0170x over previous
#include <cuda_runtime.h>

#define B 16
#define T 512
#define D 256
#define HS 512
#define DA 64
#define R 8
#define G4 2048
#define NCTA 128
#define SCAN_THREADS 512
#define TC 64
#define NCH (T/TC)   // 8
#define WROW 36      // floats per Wd row (144 B): conflict-free vs 128B pattern

// -------- scratch (static device arrays: allocation-free) --------
__device__ float g_s [B*T*R];
__device__ float g_e [B*T*R];
__device__ float g_iz[B*T*R];
__device__ float g_S [B*NCH*R*D];                // per-chunk e*x sums, 1 MB
__device__ float g_M [B*T*D];
__device__ float g_gates[(size_t)B*T*G4];        // 64 MB
__device__ float g_hbuf[2][HS*B];                // [h][b] transposed, double-buffered
__device__ unsigned g_arrive[NCTA*32];           // barrier slots, 128B stride

typedef unsigned long long ull;

// ---- packed f32x2 helpers (Blackwell: 2 MACs / inst) ----
__device__ __forceinline__ void ffma2(ull& d, ull a, ull b){
    asm("fma.rn.f32x2 %0, %1, %2, %0;" : "+l"(d) : "l"(a), "l"(b));
}
__device__ __forceinline__ ull addf2(ull a, ull b){
    ull d; asm("add.rn.f32x2 %0, %1, %2;" : "=l"(d) : "l"(a), "l"(b)); return d;
}
__device__ __forceinline__ ull pack2(float x){
    ull r; asm("mov.b64 %0, {%1, %1};" : "=l"(r) : "r"(__float_as_uint(x))); return r;
}
__device__ __forceinline__ ull dbl2u(double d){ return (ull)__double_as_longlong(d); }
__device__ __forceinline__ float lo2(ull v){ return __uint_as_float((unsigned)v); }
__device__ __forceinline__ float hi2(ull v){ return __uint_as_float((unsigned)(v>>32)); }

// fast tanh: 1 - 2/(e^{2x}+1). Saturates to +/-1, no NaN, ~1e-6 rel err.
__device__ __forceinline__ float ftanh(float x){
    return 1.f - 2.f/(__expf(2.f*x) + 1.f);
}
__device__ __forceinline__ float fsig(float x){
    return 1.f/(1.f + __expf(-x));
}

__device__ __forceinline__ void st_release(unsigned* p, unsigned v){
    asm volatile("st.release.gpu.global.u32 [%0], %1;" :: "l"(p), "r"(v) : "memory");
}
__device__ __forceinline__ unsigned ld_acquire(const unsigned* p){
    unsigned v;
    asm volatile("ld.acquire.gpu.global.u32 %0, [%1];" : "=r"(v) : "l"(p) : "memory");
    return v;
}

// ---------------- init: reset barrier slots + h0 ----------------
__global__ void k_init() {
    int tid = threadIdx.x;
    for (int i = tid; i < 2*HS*B; i += blockDim.x)
        ((float*)g_hbuf)[i] = 0.f;
    for (int i = tid; i < NCTA*32; i += blockDim.x)
        g_arrive[i] = 0u;
}

// ------- s[b,t,r] = tanh(x@W1 + b1) @ W2 + b2  (8 rows / block) -------
__global__ void k_s(const float* __restrict__ x, const float* __restrict__ w1,
                    const float* __restrict__ b1, const float* __restrict__ w2,
                    const float* __restrict__ b2) {
    __shared__ float xs[8][D];
    __shared__ float h1[8][DA];
    int tid = threadIdx.x;                 // 256
    int row0 = blockIdx.x * 8;             // row = b*T + t
    for (int i = tid; i < 8*D; i += 256)
        xs[i/D][i%D] = x[(size_t)row0*D + i];
    __syncthreads();
    int a = tid & 63, rq = tid >> 6;
    float acc0 = b1[a], acc1 = b1[a];
    #pragma unroll 4
    for (int d = 0; d < D; d++) {
        float w = w1[d*DA + a];
        acc0 += xs[rq][d]   * w;
        acc1 += xs[rq+4][d] * w;
    }
    h1[rq][a]   = tanhf(acc0);
    h1[rq+4][a] = tanhf(acc1);
    __syncthreads();
    if (tid < 64) {
        int rr = tid >> 3, r = tid & 7;
        float acc = b2[r];
        #pragma unroll 8
        for (int a2 = 0; a2 < DA; a2++)
            acc += h1[rr][a2] * w2[a2*R + r];
        g_s[(size_t)(row0+rr)*R + r] = acc;
    }
}

// ------- running softmax denominators: e = exp(s), iz = 1/cumsum(e) -------
__global__ void k_cumsum() {
    int tid = threadIdx.x;
    if (tid >= B*R) return;
    int b = tid >> 3, r = tid & 7;
    const float* sp = &g_s [(size_t)b*T*R + r];
    float*       ep = &g_e [(size_t)b*T*R + r];
    float*       zp = &g_iz[(size_t)b*T*R + r];
    float z = 0.f;
    #pragma unroll 4
    for (int t = 0; t < T; t++) {
        float e = expf(sp[t*R]);
        z += e;
        ep[t*R] = e;
        zp[t*R] = 1.0f / z;
    }
}

// ------- pass 1: per-chunk sums S[b,ch,r,d] = sum_{j in chunk} e[j,r]*x[j,d] -------
__global__ void k_M1(const float* __restrict__ x) {
    __shared__ float es[TC*R];
    int b = blockIdx.x >> 3, ch = blockIdx.x & 7;
    int tid = threadIdx.x;                 // 256
    int t0 = ch*TC;
    for (int i = tid; i < TC*R; i += 256)
        es[i] = g_e[((size_t)b*T + t0)*R + i];
    __syncthreads();
    int d = tid;
    float acc[R] = {};
    const float* xp = &x[((size_t)b*T + t0)*D + d];
    #pragma unroll 4
    for (int j = 0; j < TC; j++) {
        float xv = xp[(size_t)j*D];
        #pragma unroll
        for (int r = 0; r < R; r++) acc[r] += es[j*R + r] * xv;
    }
    float* sp = &g_S[((size_t)(b*NCH + ch)*R)*D + d];
    #pragma unroll
    for (int r = 0; r < R; r++) sp[r*D] = acc[r];
}

// ------- pass 2: within-chunk weighted cumsum, seeded by chunk prefix -------
__global__ void k_M2(const float* __restrict__ x) {
    __shared__ float4 es[TC*2];
    __shared__ float4 zs[TC*2];
    int bi = blockIdx.x;
    int b = bi >> 4, dh = (bi >> 3) & 1, ch = bi & 7;
    int tid = threadIdx.x;                 // 128
    int t0 = ch*TC;
    const float4* eg = (const float4*)&g_e [((size_t)b*T + t0)*R];
    const float4* zg = (const float4*)&g_iz[((size_t)b*T + t0)*R];
    for (int i = tid; i < TC*2; i += 128) { es[i] = eg[i]; zs[i] = zg[i]; }
    __syncthreads();
    int d = dh*128 + tid;
    float4 clo = {0,0,0,0}, chi = {0,0,0,0};
    for (int c = 0; c < ch; c++) {
        const float* sp = &g_S[((size_t)(b*NCH + c)*R)*D + d];
        clo.x += sp[0];   clo.y += sp[D];   clo.z += sp[2*D]; clo.w += sp[3*D];
        chi.x += sp[4*D]; chi.y += sp[5*D]; chi.z += sp[6*D]; chi.w += sp[7*D];
    }
    const float* xp = &x[((size_t)b*T + t0)*D + d];
    float*       mp = &g_M[((size_t)b*T + t0)*D + d];
    for (int j = 0; j < TC; j += 4) {
        float xv[4];
        #pragma unroll
        for (int u = 0; u < 4; u++) xv[u] = xp[(size_t)(j+u)*D];
        float mo[4];
        #pragma unroll
        for (int u = 0; u < 4; u++) {
            float4 ea = es[2*(j+u)], eb = es[2*(j+u)+1];
            clo.x += ea.x*xv[u]; clo.y += ea.y*xv[u]; clo.z += ea.z*xv[u]; clo.w += ea.w*xv[u];
            chi.x += eb.x*xv[u]; chi.y += eb.y*xv[u]; chi.z += eb.z*xv[u]; chi.w += eb.w*xv[u];
            float4 za = zs[2*(j+u)], zb = zs[2*(j+u)+1];
            mo[u] = (clo.x*za.x + clo.y*za.y + clo.z*za.z + clo.w*za.w
                   + chi.x*zb.x + chi.y*zb.y + chi.z*zb.z + chi.w*zb.w) * 0.125f;
        }
        #pragma unroll
        for (int u = 0; u < 4; u++) mp[(size_t)(j+u)*D] = mo[u];
    }
}

// ------- gates = M(8192x256) @ W_i(256x2048) + bias, 128x128x16 / 8x8 tiles -------
#define GBM 128
#define GBN 128
#define GBK 16
__global__ void __launch_bounds__(256)
k_gemm(const float* __restrict__ Wi, const float* __restrict__ bias) {
    __shared__ float As[GBK][GBM+4];
    __shared__ float Bs[GBK][GBN+4];
    int tid = threadIdx.x;             // 256
    int tx = tid & 15, ty = tid >> 4;
    int rb = blockIdx.y * GBM, nb = blockIdx.x * GBN;
    ull c2[8][4] = {};
    for (int kb = 0; kb < D; kb += GBK) {
        #pragma unroll
        for (int j = 0; j < 2; j++) {
            int lin = tid + j*256;
            int m = lin >> 2, kq = (lin & 3)*4;
            float4 v = *(const float4*)&g_M[(size_t)(rb+m)*D + kb + kq];
            As[kq+0][m] = v.x; As[kq+1][m] = v.y;
            As[kq+2][m] = v.z; As[kq+3][m] = v.w;
        }
        #pragma unroll
        for (int j = 0; j < 2; j++) {
            int lin = tid + j*256;
            int kk2 = lin >> 5, nq = (lin & 31)*4;
            *(float4*)&Bs[kk2][nq] = *(const float4*)&Wi[(size_t)(kb+kk2)*G4 + nb + nq];
        }
        __syncthreads();
        #pragma unroll
        for (int kk = 0; kk < GBK; kk++) {
            float4 a0 = *(const float4*)&As[kk][ty*8];
            float4 a1 = *(const float4*)&As[kk][ty*8+4];
            double2 b0 = *(const double2*)&Bs[kk][tx*8];
            double2 b1 = *(const double2*)&Bs[kk][tx*8+4];
            ull bx0 = dbl2u(b0.x), bx1 = dbl2u(b0.y);
            ull bx2 = dbl2u(b1.x), bx3 = dbl2u(b1.y);
            float av[8] = {a0.x,a0.y,a0.z,a0.w,a1.x,a1.y,a1.z,a1.w};
            #pragma unroll
            for (int i = 0; i < 8; i++) {
                ull ap = pack2(av[i]);
                ffma2(c2[i][0], ap, bx0); ffma2(c2[i][1], ap, bx1);
                ffma2(c2[i][2], ap, bx2); ffma2(c2[i][3], ap, bx3);
            }
        }
        __syncthreads();
    }
    float4 bv0 = *(const float4*)&bias[nb + tx*8];
    float4 bv1 = *(const float4*)&bias[nb + tx*8 + 4];
    #pragma unroll
    for (int i = 0; i < 8; i++) {
        int row = rb + ty*8 + i;
        float4 o0 = make_float4(lo2(c2[i][0])+bv0.x, hi2(c2[i][0])+bv0.y,
                                lo2(c2[i][1])+bv0.z, hi2(c2[i][1])+bv0.w);
        float4 o1 = make_float4(lo2(c2[i][2])+bv1.x, hi2(c2[i][2])+bv1.y,
                                lo2(c2[i][3])+bv1.z, hi2(c2[i][3])+bv1.w);
        *(float4*)&g_gates[(size_t)row*G4 + nb + tx*8]     = o0;
        *(float4*)&g_gates[(size_t)row*G4 + nb + tx*8 + 4] = o1;
    }
}

// ------- persistent LSTM scan v6 -------
// CTA k owns h-indices [4k,4k+4). W in SMEM as duplicated f32x2 pairs with
// 144B row stride (conflict-free vs the 128B access pattern): dot has zero
// MOV packing. Fusion by 64 threads (2 warps) using MUFU-based tanh/sigmoid.
// Early release: named bar.sync(1,64) then tid0 st.release (no full
// syncthreads on the release path). Hot-spin acquire polls.
__global__ void __launch_bounds__(SCAN_THREADS, 1)
k_scan(const float* __restrict__ Whh, float* __restrict__ out) {
    extern __shared__ float sm[];
    float* Wd  = sm;                      // [512][WROW=36] pairs, 73,728 B
    float* Hs  = sm + HS*WROW;            // [512][16] 32 KB
    float* red = Hs + 8192;               // [16 warps][16 c][20-pad b] 20 KB
    float* sg  = red + 5120;              // [16 c][16 b]
    int tid = threadIdx.x;
    int k = blockIdx.x;
    int lane = tid & 31, warp = tid >> 5;
    int cx = lane & 3, by = (lane>>2)&3, ksub = lane>>4;
    int kbase = warp*32 + ksub;            // thread covers h = kbase + 2*i, i<16

    // stage duplicated W once: pair {w,w} at Wd[h*36 + c*2], c = gate*4 + j
    for (int idx = tid; idx < HS*16; idx += SCAN_THREADS) {
        int h = idx >> 4, c = idx & 15;
        float w = Whh[(size_t)h*G4 + (c>>2)*HS + k*4 + (c&3)];
        Wd[h*WROW + c*2]     = w;
        Wd[h*WROW + c*2 + 1] = w;
    }
    __syncthreads();

    // fusion mapping (tid < 64): fb = tid>>2 (batch), fj = tid&3 (j within 4)
    int fb = tid >> 2, fj = tid & 3;
    float creg = 0.f;
    float gx[4];
    if (tid < 64) {
        const float* gp = &g_gates[((size_t)fb*T + 0)*G4 + k*4 + fj];
        #pragma unroll
        for (int g = 0; g < 4; g++) gx[g] = __ldg(gp + g*HS);
    }

    float* hid_out = out;                         // (B,T,HS)
    float* ht_out  = out + (size_t)B*T*HS;        // (B,HS)
    float* ct_out  = ht_out + B*HS;               // (B,HS)

    for (int t = 0; t < T; t++) {
        // stage H into SMEM (32 KB, coalesced, L1-bypassing)
        {
            const float4* hb = (const float4*)&g_hbuf[t&1][0];
            float4* hs4 = (float4*)Hs;
            #pragma unroll
            for (int j = 0; j < 4; j++)
                hs4[tid + j*512] = __ldcv(hb + tid + j*512);
        }
        __syncthreads();

        // 4x4 outer-product dot, W pairs from SMEM (conflict-free rows)
        ull acc[4][2] = {};
        #pragma unroll
        for (int i = 0; i < 16; i++) {
            int h = kbase + 2*i;
            const ull* wq = (const ull*)(Wd + h*WROW + cx*8);
            ull w0 = wq[0], w1 = wq[1], w2 = wq[2], w3 = wq[3];
            double2 hd = *(const double2*)&Hs[h*16 + by*4];
            ull hx = dbl2u(hd.x), hy = dbl2u(hd.y);
            ffma2(acc[0][0], w0, hx); ffma2(acc[0][1], w0, hy);
            ffma2(acc[1][0], w1, hx); ffma2(acc[1][1], w1, hy);
            ffma2(acc[2][0], w2, hx); ffma2(acc[2][1], w2, hy);
            ffma2(acc[3][0], w3, hx); ffma2(acc[3][1], w3, hy);
        }
        // reduce ksub pairs via shfl (lanes xor 16 share (cx,by))
        #pragma unroll
        for (int q = 0; q < 4; q++) {
            acc[q][0] = addf2(acc[q][0], __shfl_xor_sync(0xffffffffu, acc[q][0], 16));
            acc[q][1] = addf2(acc[q][1], __shfl_xor_sync(0xffffffffu, acc[q][1], 16));
        }
        if (ksub == 0) {
            float* rp = &red[warp*320 + (cx*4)*20 + by*4];
            #pragma unroll
            for (int q = 0; q < 4; q++) {
                float4 v = make_float4(lo2(acc[q][0]), hi2(acc[q][0]),
                                       lo2(acc[q][1]), hi2(acc[q][1]));
                *(float4*)(rp + q*20) = v;
            }
        }
        __syncthreads();

        // reduce 16 warps: thread tid<256 owns (c = tid>>4, b = tid&15)
        if (tid < 256) {
            int c = tid >> 4, b = tid & 15;
            float s = 0.f;
            #pragma unroll
            for (int w = 0; w < 16; w++) s += red[w*320 + c*20 + b];
            sg[tid] = s;
        }
        __syncthreads();

        // gate fusion: 64 threads (warps 0-1), fast MUFU tanh/sigmoid,
        // then early release via named barrier + tid0 st.release
        if (tid < 64) {
            float gi = sg[( 0 + fj)*16 + fb] + gx[0];
            float gf = sg[( 4 + fj)*16 + fb] + gx[1];
            float gg = sg[( 8 + fj)*16 + fb] + gx[2];
            float go = sg[(12 + fj)*16 + fb] + gx[3];
            float iv = fsig(gi);
            float fv = fsig(gf);
            float gv = ftanh(gg);
            float ov = fsig(go);
            creg = fv*creg + iv*gv;
            float hv = ov * ftanh(creg);
            int hj = k*4 + fj;
            hid_out[((size_t)fb*T + t)*HS + hj] = hv;
            g_hbuf[(t+1)&1][hj*B + fb] = hv;     // transposed [h][b]
            if (t == T-1) { ht_out[fb*HS + hj] = hv; ct_out[fb*HS + hj] = creg; }
            asm volatile("bar.sync 1, 64;" ::: "memory");   // order h pub (warps 0-1)
            if (tid == 0) st_release(&g_arrive[k*32], (unsigned)(t+1));
            // prefetch next step's gates_x while the grid converges
            if (t+1 < T) {
                const float* gp = &g_gates[((size_t)fb*T + (t+1))*G4 + k*4 + fj];
                #pragma unroll
                for (int g = 0; g < 4; g++) gx[g] = __ldg(gp + g*HS);
            }
        }

        // grid barrier: hot-spin acquire polls on per-CTA slots
        if (tid < NCTA) {
            const unsigned* slot = &g_arrive[tid*32];
            int spins = 0;
            while (ld_acquire(slot) < (unsigned)(t+1)) {
                if (++spins > 512) __nanosleep(40);
            }
        }
        __syncthreads();
    }
}

extern "C" void kernel_launch(void* const* d_in, const int* in_sizes, int n_in,
                              void* d_out, int out_size) {
    const float* x    = (const float*)d_in[0];
    const float* w1   = (const float*)d_in[1];
    const float* b1   = (const float*)d_in[2];
    const float* w2   = (const float*)d_in[3];
    const float* b2   = (const float*)d_in[4];
    const float* Wi   = (const float*)d_in[5];
    const float* Whh  = (const float*)d_in[6];
    const float* bias = (const float*)d_in[7];
    float* out = (float*)d_out;

    (void)in_sizes; (void)n_in; (void)out_size;

    k_init<<<1, 256>>>();
    k_s<<<(B*T)/8, 256>>>(x, w1, b1, w2, b2);
    k_cumsum<<<1, 128>>>();
    k_M1<<<B*NCH, 256>>>(x);
    k_M2<<<B*2*NCH, 128>>>(x);
    dim3 gg(G4/GBN, (B*T)/GBM);
    k_gemm<<<gg, 256>>>(Wi, bias);

    size_t smem = (size_t)(HS*WROW + 8192 + 5120 + 256) * sizeof(float);  // 128,000 B
    cudaFuncSetAttribute(k_scan, cudaFuncAttributeMaxDynamicSharedMemorySize, (int)smem);
    k_scan<<<NCTA, SCAN_THREADS, smem>>>(Whh, out);
}

// round 8
// speedup vs baseline: 1.1446x; 1.1255x over previous
#include <cuda_runtime.h>

#define B 16
#define T 512
#define D 256
#define HS 512
#define DA 64
#define R 8
#define G4 2048
#define NCTA 128
#define SCAN_THREADS 512
#define TC 64
#define NCH (T/TC)   // 8

// -------- scratch (static device arrays: allocation-free) --------
__device__ float g_s [B*T*R];
__device__ float g_e [B*T*R];
__device__ float g_iz[B*T*R];
__device__ float g_S [B*NCH*R*D];                // per-chunk e*x sums, 1 MB
__device__ float g_M [B*T*D];
__device__ float g_gates[(size_t)B*T*G4];        // 64 MB
__device__ float g_hbuf[2][HS*B];                // [h][b] transposed, double-buffered
__device__ unsigned g_arrive[NCTA*32];           // barrier slots, 128B stride

typedef unsigned long long ull;

// ---- packed f32x2 helpers (Blackwell: 2 MACs / inst) ----
__device__ __forceinline__ void ffma2(ull& d, ull a, ull b){
    asm("fma.rn.f32x2 %0, %1, %2, %0;" : "+l"(d) : "l"(a), "l"(b));
}
__device__ __forceinline__ ull addf2(ull a, ull b){
    ull d; asm("add.rn.f32x2 %0, %1, %2;" : "=l"(d) : "l"(a), "l"(b)); return d;
}
__device__ __forceinline__ ull pack2(float x){
    ull r; asm("mov.b64 %0, {%1, %1};" : "=l"(r) : "r"(__float_as_uint(x))); return r;
}
__device__ __forceinline__ ull dbl2u(double d){ return (ull)__double_as_longlong(d); }
__device__ __forceinline__ float lo2(ull v){ return __uint_as_float((unsigned)v); }
__device__ __forceinline__ float hi2(ull v){ return __uint_as_float((unsigned)(v>>32)); }

__device__ __forceinline__ void st_release(unsigned* p, unsigned v){
    asm volatile("st.release.gpu.global.u32 [%0], %1;" :: "l"(p), "r"(v) : "memory");
}
__device__ __forceinline__ unsigned ld_acquire(const unsigned* p){
    unsigned v;
    asm volatile("ld.acquire.gpu.global.u32 %0, [%1];" : "=r"(v) : "l"(p) : "memory");
    return v;
}

// ---------------- init: reset barrier slots + h0 ----------------
__global__ void k_init() {
    int tid = threadIdx.x;
    for (int i = tid; i < 2*HS*B; i += blockDim.x)
        ((float*)g_hbuf)[i] = 0.f;
    for (int i = tid; i < NCTA*32; i += blockDim.x)
        g_arrive[i] = 0u;
}

// ------- s[b,t,r] = tanh(x@W1 + b1) @ W2 + b2  (8 rows / block) -------
__global__ void k_s(const float* __restrict__ x, const float* __restrict__ w1,
                    const float* __restrict__ b1, const float* __restrict__ w2,
                    const float* __restrict__ b2) {
    __shared__ float xs[8][D];
    __shared__ float h1[8][DA];
    int tid = threadIdx.x;                 // 256
    int row0 = blockIdx.x * 8;             // row = b*T + t
    for (int i = tid; i < 8*D; i += 256)
        xs[i/D][i%D] = x[(size_t)row0*D + i];
    __syncthreads();
    int a = tid & 63, rq = tid >> 6;
    float acc0 = b1[a], acc1 = b1[a];
    #pragma unroll 4
    for (int d = 0; d < D; d++) {
        float w = w1[d*DA + a];
        acc0 += xs[rq][d]   * w;
        acc1 += xs[rq+4][d] * w;
    }
    h1[rq][a]   = tanhf(acc0);
    h1[rq+4][a] = tanhf(acc1);
    __syncthreads();
    if (tid < 64) {
        int rr = tid >> 3, r = tid & 7;
        float acc = b2[r];
        #pragma unroll 8
        for (int a2 = 0; a2 < DA; a2++)
            acc += h1[rr][a2] * w2[a2*R + r];
        g_s[(size_t)(row0+rr)*R + r] = acc;
    }
}

// ------- running softmax denominators: e = exp(s), iz = 1/cumsum(e) -------
__global__ void k_cumsum() {
    int tid = threadIdx.x;
    if (tid >= B*R) return;
    int b = tid >> 3, r = tid & 7;
    const float* sp = &g_s [(size_t)b*T*R + r];
    float*       ep = &g_e [(size_t)b*T*R + r];
    float*       zp = &g_iz[(size_t)b*T*R + r];
    float z = 0.f;
    #pragma unroll 4
    for (int t = 0; t < T; t++) {
        float e = expf(sp[t*R]);
        z += e;
        ep[t*R] = e;
        zp[t*R] = 1.0f / z;
    }
}

// ------- pass 1: per-chunk sums S[b,ch,r,d] = sum_{j in chunk} e[j,r]*x[j,d] -------
__global__ void k_M1(const float* __restrict__ x) {
    __shared__ float es[TC*R];
    int b = blockIdx.x >> 3, ch = blockIdx.x & 7;
    int tid = threadIdx.x;                 // 256
    int t0 = ch*TC;
    for (int i = tid; i < TC*R; i += 256)
        es[i] = g_e[((size_t)b*T + t0)*R + i];
    __syncthreads();
    int d = tid;
    float acc[R] = {};
    const float* xp = &x[((size_t)b*T + t0)*D + d];
    #pragma unroll 4
    for (int j = 0; j < TC; j++) {
        float xv = xp[(size_t)j*D];
        #pragma unroll
        for (int r = 0; r < R; r++) acc[r] += es[j*R + r] * xv;
    }
    float* sp = &g_S[((size_t)(b*NCH + ch)*R)*D + d];
    #pragma unroll
    for (int r = 0; r < R; r++) sp[r*D] = acc[r];
}

// ------- pass 2: within-chunk weighted cumsum, seeded by chunk prefix -------
__global__ void k_M2(const float* __restrict__ x) {
    __shared__ float4 es[TC*2];
    __shared__ float4 zs[TC*2];
    int bi = blockIdx.x;
    int b = bi >> 4, dh = (bi >> 3) & 1, ch = bi & 7;
    int tid = threadIdx.x;                 // 128
    int t0 = ch*TC;
    const float4* eg = (const float4*)&g_e [((size_t)b*T + t0)*R];
    const float4* zg = (const float4*)&g_iz[((size_t)b*T + t0)*R];
    for (int i = tid; i < TC*2; i += 128) { es[i] = eg[i]; zs[i] = zg[i]; }
    __syncthreads();
    int d = dh*128 + tid;
    float4 clo = {0,0,0,0}, chi = {0,0,0,0};
    for (int c = 0; c < ch; c++) {
        const float* sp = &g_S[((size_t)(b*NCH + c)*R)*D + d];
        clo.x += sp[0];   clo.y += sp[D];   clo.z += sp[2*D]; clo.w += sp[3*D];
        chi.x += sp[4*D]; chi.y += sp[5*D]; chi.z += sp[6*D]; chi.w += sp[7*D];
    }
    const float* xp = &x[((size_t)b*T + t0)*D + d];
    float*       mp = &g_M[((size_t)b*T + t0)*D + d];
    for (int j = 0; j < TC; j += 4) {
        float xv[4];
        #pragma unroll
        for (int u = 0; u < 4; u++) xv[u] = xp[(size_t)(j+u)*D];
        float mo[4];
        #pragma unroll
        for (int u = 0; u < 4; u++) {
            float4 ea = es[2*(j+u)], eb = es[2*(j+u)+1];
            clo.x += ea.x*xv[u]; clo.y += ea.y*xv[u]; clo.z += ea.z*xv[u]; clo.w += ea.w*xv[u];
            chi.x += eb.x*xv[u]; chi.y += eb.y*xv[u]; chi.z += eb.z*xv[u]; chi.w += eb.w*xv[u];
            float4 za = zs[2*(j+u)], zb = zs[2*(j+u)+1];
            mo[u] = (clo.x*za.x + clo.y*za.y + clo.z*za.z + clo.w*za.w
                   + chi.x*zb.x + chi.y*zb.y + chi.z*zb.z + chi.w*zb.w) * 0.125f;
        }
        #pragma unroll
        for (int u = 0; u < 4; u++) mp[(size_t)(j+u)*D] = mo[u];
    }
}

// ------- gates = M(8192x256) @ W_i(256x2048) + bias, 128x128x16 / 8x8 tiles -------
#define GBM 128
#define GBN 128
#define GBK 16
__global__ void __launch_bounds__(256)
k_gemm(const float* __restrict__ Wi, const float* __restrict__ bias) {
    __shared__ float As[GBK][GBM+4];
    __shared__ float Bs[GBK][GBN+4];
    int tid = threadIdx.x;             // 256
    int tx = tid & 15, ty = tid >> 4;
    int rb = blockIdx.y * GBM, nb = blockIdx.x * GBN;
    ull c2[8][4] = {};
    for (int kb = 0; kb < D; kb += GBK) {
        #pragma unroll
        for (int j = 0; j < 2; j++) {
            int lin = tid + j*256;
            int m = lin >> 2, kq = (lin & 3)*4;
            float4 v = *(const float4*)&g_M[(size_t)(rb+m)*D + kb + kq];
            As[kq+0][m] = v.x; As[kq+1][m] = v.y;
            As[kq+2][m] = v.z; As[kq+3][m] = v.w;
        }
        #pragma unroll
        for (int j = 0; j < 2; j++) {
            int lin = tid + j*256;
            int kk2 = lin >> 5, nq = (lin & 31)*4;
            *(float4*)&Bs[kk2][nq] = *(const float4*)&Wi[(size_t)(kb+kk2)*G4 + nb + nq];
        }
        __syncthreads();
        #pragma unroll
        for (int kk = 0; kk < GBK; kk++) {
            float4 a0 = *(const float4*)&As[kk][ty*8];
            float4 a1 = *(const float4*)&As[kk][ty*8+4];
            double2 b0 = *(const double2*)&Bs[kk][tx*8];
            double2 b1 = *(const double2*)&Bs[kk][tx*8+4];
            ull bx0 = dbl2u(b0.x), bx1 = dbl2u(b0.y);
            ull bx2 = dbl2u(b1.x), bx3 = dbl2u(b1.y);
            float av[8] = {a0.x,a0.y,a0.z,a0.w,a1.x,a1.y,a1.z,a1.w};
            #pragma unroll
            for (int i = 0; i < 8; i++) {
                ull ap = pack2(av[i]);
                ffma2(c2[i][0], ap, bx0); ffma2(c2[i][1], ap, bx1);
                ffma2(c2[i][2], ap, bx2); ffma2(c2[i][3], ap, bx3);
            }
        }
        __syncthreads();
    }
    float4 bv0 = *(const float4*)&bias[nb + tx*8];
    float4 bv1 = *(const float4*)&bias[nb + tx*8 + 4];
    #pragma unroll
    for (int i = 0; i < 8; i++) {
        int row = rb + ty*8 + i;
        float4 o0 = make_float4(lo2(c2[i][0])+bv0.x, hi2(c2[i][0])+bv0.y,
                                lo2(c2[i][1])+bv0.z, hi2(c2[i][1])+bv0.w);
        float4 o1 = make_float4(lo2(c2[i][2])+bv1.x, hi2(c2[i][2])+bv1.y,
                                lo2(c2[i][3])+bv1.z, hi2(c2[i][3])+bv1.w);
        *(float4*)&g_gates[(size_t)row*G4 + nb + tx*8]     = o0;
        *(float4*)&g_gates[(size_t)row*G4 + nb + tx*8 + 4] = o1;
    }
}

// ------- persistent LSTM scan (R5 structure, HOT-SPIN poll experiment) -------
// Identical to the 2075us R5 kernel except the grid-barrier poll: pure
// hot-spin acquire loop, NO __nanosleep. Single-variable experiment to
// attribute the barrier-detection latency.
__global__ void __launch_bounds__(SCAN_THREADS, 1)
k_scan(const float* __restrict__ Whh, float* __restrict__ out) {
    extern __shared__ float sm[];
    float* Hs  = sm;                  // [512][16]  32 KB
    float* red = sm + 8192;           // [16 warps][16 c][20-pad b] 20 KB
    float* sg  = sm + 8192 + 5120;    // [16 c][16 b]
    int tid = threadIdx.x;
    int k = blockIdx.x;
    int lane = tid & 31, warp = tid >> 5;
    int cx = lane & 3, by = (lane>>2)&3, ksub = lane>>4;
    int kbase = warp*32 + ksub;            // thread covers h = kbase + 2*i, i<16
    int bb = tid >> 2, j2 = tid & 3;       // fusion mapping (tid<64)
    float creg = 0.f;

    // preload W slice into registers: wr[i] = Whh[kbase+2i][cx*HS + k*4 .. +3]
    float4 wr[16];
    #pragma unroll
    for (int i = 0; i < 16; i++)
        wr[i] = *(const float4*)&Whh[(size_t)(kbase + 2*i)*G4 + cx*HS + k*4];

    float* hid_out = out;                         // (B,T,HS)
    float* ht_out  = out + (size_t)B*T*HS;        // (B,HS)
    float* ct_out  = ht_out + B*HS;               // (B,HS)

    for (int t = 0; t < T; t++) {
        // prefetch gates_x for fusion threads (hidden under staging+dot)
        float gx0=0.f, gx1=0.f, gx2=0.f, gx3=0.f;
        if (tid < 64) {
            const float* gp = &g_gates[((size_t)bb*T + t)*G4 + k*4 + j2];
            gx0 = __ldg(gp); gx1 = __ldg(gp + HS);
            gx2 = __ldg(gp + 2*HS); gx3 = __ldg(gp + 3*HS);
        }

        // stage H into SMEM (exactly 32 KB, coalesced, L1-bypassing)
        {
            const float4* hb = (const float4*)&g_hbuf[t&1][0];
            float4* hs4 = (float4*)Hs;
            #pragma unroll
            for (int j = 0; j < 4; j++)
                hs4[tid + j*512] = __ldcv(hb + tid + j*512);
        }
        __syncthreads();

        // 4x4 outer-product dot over this thread's 32-h slice (W regs, H smem)
        ull acc[4][2] = {};
        #pragma unroll
        for (int i = 0; i < 16; i++) {
            double2 hd = *(const double2*)&Hs[(kbase + 2*i)*16 + by*4];
            ull hx = dbl2u(hd.x), hy = dbl2u(hd.y);
            ull w0 = pack2(wr[i].x), w1 = pack2(wr[i].y);
            ull w2 = pack2(wr[i].z), w3 = pack2(wr[i].w);
            ffma2(acc[0][0], w0, hx); ffma2(acc[0][1], w0, hy);
            ffma2(acc[1][0], w1, hx); ffma2(acc[1][1], w1, hy);
            ffma2(acc[2][0], w2, hx); ffma2(acc[2][1], w2, hy);
            ffma2(acc[3][0], w3, hx); ffma2(acc[3][1], w3, hy);
        }
        // reduce ksub pairs via shfl (lanes xor 16 share (cx,by))
        #pragma unroll
        for (int q = 0; q < 4; q++) {
            acc[q][0] = addf2(acc[q][0], __shfl_xor_sync(0xffffffffu, acc[q][0], 16));
            acc[q][1] = addf2(acc[q][1], __shfl_xor_sync(0xffffffffu, acc[q][1], 16));
        }
        if (ksub == 0) {
            float* rp = &red[warp*320 + (cx*4)*20 + by*4];
            #pragma unroll
            for (int q = 0; q < 4; q++) {
                float4 v = make_float4(lo2(acc[q][0]), hi2(acc[q][0]),
                                       lo2(acc[q][1]), hi2(acc[q][1]));
                *(float4*)(rp + q*20) = v;
            }
        }
        __syncthreads();

        // reduce 16 warps: thread tid<256 owns (c = tid>>4, b = tid&15)
        if (tid < 256) {
            int c = tid >> 4, b = tid & 15;
            float s = 0.f;
            #pragma unroll
            for (int w = 0; w < 16; w++) s += red[w*320 + c*20 + b];
            sg[tid] = s;
        }
        __syncthreads();

        // gate fusion: thread = (bb, j2)
        if (tid < 64) {
            float gi = sg[( 0 + j2)*16 + bb] + gx0;
            float gf = sg[( 4 + j2)*16 + bb] + gx1;
            float gg = sg[( 8 + j2)*16 + bb] + gx2;
            float go = sg[(12 + j2)*16 + bb] + gx3;
            float iv = 1.f/(1.f + __expf(-gi));
            float fv = 1.f/(1.f + __expf(-gf));
            float gv = tanhf(gg);
            float ov = 1.f/(1.f + __expf(-go));
            creg = fv*creg + iv*gv;
            float hv = ov * tanhf(creg);
            int hj = k*4 + j2;
            hid_out[((size_t)bb*T + t)*HS + hj] = hv;
            g_hbuf[(t+1)&1][hj*B + bb] = hv;     // transposed [h][b]
            if (t == T-1) { ht_out[bb*HS + hj] = hv; ct_out[bb*HS + hj] = creg; }
        }
        __syncthreads();   // order h writes (cta-wide) before tid0's release

        if (tid == 0) st_release(&g_arrive[k*32], (unsigned)(t+1));
        // grid barrier: pure hot-spin acquire polls (NO nanosleep) — the
        // single experimental variable vs the 2075us R5 kernel.
        if (tid < NCTA) {
            const unsigned* slot = &g_arrive[tid*32];
            while (ld_acquire(slot) < (unsigned)(t+1)) { }
        }
        __syncthreads();
    }
}

extern "C" void kernel_launch(void* const* d_in, const int* in_sizes, int n_in,
                              void* d_out, int out_size) {
    const float* x    = (const float*)d_in[0];
    const float* w1   = (const float*)d_in[1];
    const float* b1   = (const float*)d_in[2];
    const float* w2   = (const float*)d_in[3];
    const float* b2   = (const float*)d_in[4];
    const float* Wi   = (const float*)d_in[5];
    const float* Whh  = (const float*)d_in[6];
    const float* bias = (const float*)d_in[7];
    float* out = (float*)d_out;

    (void)in_sizes; (void)n_in; (void)out_size;

    k_init<<<1, 256>>>();
    k_s<<<(B*T)/8, 256>>>(x, w1, b1, w2, b2);
    k_cumsum<<<1, 128>>>();
    k_M1<<<B*NCH, 256>>>(x);
    k_M2<<<B*2*NCH, 128>>>(x);
    dim3 gg(G4/GBN, (B*T)/GBM);
    k_gemm<<<gg, 256>>>(Wi, bias);

    size_t smem = (size_t)(8192 + 5120 + 256) * sizeof(float);   // 54,272 B
    cudaFuncSetAttribute(k_scan, cudaFuncAttributeMaxDynamicSharedMemorySize, (int)smem);
    k_scan<<<NCTA, SCAN_THREADS, smem>>>(Whh, out);
}

// round 13
// speedup vs baseline: 1.2143x; 1.0608x over previous
#include <cuda_runtime.h>

#define B 16
#define T 512
#define D 256
#define HS 512
#define DA 64
#define R 8
#define G4 2048
#define NCTA 128
#define SCAN_THREADS 512
#define TC 64
#define NCH (T/TC)   // 8

// -------- scratch (static device arrays: allocation-free) --------
__device__ float g_s [B*T*R];
__device__ float g_e [B*T*R];
__device__ float g_iz[B*T*R];
__device__ float g_S [B*NCH*R*D];                // per-chunk e*x sums, 1 MB
__device__ float g_M [B*T*D];
__device__ float g_gates[(size_t)B*T*G4];        // 64 MB
__device__ float g_hbuf[2][HS*B];                // [h][b] transposed, double-buffered
__device__ unsigned g_arrive[NCTA*32];           // barrier slots, 128B stride

typedef unsigned long long ull;

// ---- packed f32x2 helpers (Blackwell: 2 MACs / inst) ----
__device__ __forceinline__ void ffma2(ull& d, ull a, ull b){
    asm("fma.rn.f32x2 %0, %1, %2, %0;" : "+l"(d) : "l"(a), "l"(b));
}
__device__ __forceinline__ ull addf2(ull a, ull b){
    ull d; asm("add.rn.f32x2 %0, %1, %2;" : "=l"(d) : "l"(a), "l"(b)); return d;
}
__device__ __forceinline__ ull pack2(float x){
    ull r; asm("mov.b64 %0, {%1, %1};" : "=l"(r) : "r"(__float_as_uint(x))); return r;
}
__device__ __forceinline__ ull dbl2u(double d){ return (ull)__double_as_longlong(d); }
__device__ __forceinline__ float lo2(ull v){ return __uint_as_float((unsigned)v); }
__device__ __forceinline__ float hi2(ull v){ return __uint_as_float((unsigned)(v>>32)); }

// fast sigmoid/tanh via MUFU (rel err ~1e-6, saturates correctly)
__device__ __forceinline__ float fsig(float x){ return 1.f/(1.f + __expf(-x)); }
__device__ __forceinline__ float ftanh(float x){ return 1.f - 2.f/(__expf(2.f*x) + 1.f); }

__device__ __forceinline__ void st_release(unsigned* p, unsigned v){
    asm volatile("st.release.gpu.global.u32 [%0], %1;" :: "l"(p), "r"(v) : "memory");
}
__device__ __forceinline__ unsigned ld_acquire(const unsigned* p){
    unsigned v;
    asm volatile("ld.acquire.gpu.global.u32 %0, [%1];" : "=r"(v) : "l"(p) : "memory");
    return v;
}
// 16B L1-bypassing L2-served load (NOT .cv — .cv refetches from DRAM)
__device__ __forceinline__ void ldg_16_l2(void* dst, const void* src){
    ull a, b;
    asm volatile("ld.volatile.global.v2.u64 {%0, %1}, [%2];"
                 : "=l"(a), "=l"(b) : "l"(src) : "memory");
    ((ull*)dst)[0] = a; ((ull*)dst)[1] = b;
}
// strong gpu-scope scalar store (h publish)
__device__ __forceinline__ void stg_rel_f32(float* p, float v){
    asm volatile("st.relaxed.gpu.global.b32 [%0], %1;"
                 :: "l"(p), "r"(__float_as_uint(v)) : "memory");
}

// ---------------- init: reset barrier slots + h0 ----------------
__global__ void k_init() {
    int tid = threadIdx.x;
    for (int i = tid; i < 2*HS*B; i += blockDim.x)
        ((float*)g_hbuf)[i] = 0.f;
    for (int i = tid; i < NCTA*32; i += blockDim.x)
        g_arrive[i] = 0u;
}

// ------- s[b,t,r] = tanh(x@W1 + b1) @ W2 + b2  (8 rows / block) -------
__global__ void k_s(const float* __restrict__ x, const float* __restrict__ w1,
                    const float* __restrict__ b1, const float* __restrict__ w2,
                    const float* __restrict__ b2) {
    __shared__ float xs[8][D];
    __shared__ float h1[8][DA];
    int tid = threadIdx.x;                 // 256
    int row0 = blockIdx.x * 8;             // row = b*T + t
    for (int i = tid; i < 8*D; i += 256)
        xs[i/D][i%D] = x[(size_t)row0*D + i];
    __syncthreads();
    int a = tid & 63, rq = tid >> 6;
    float acc0 = b1[a], acc1 = b1[a];
    #pragma unroll 4
    for (int d = 0; d < D; d++) {
        float w = w1[d*DA + a];
        acc0 += xs[rq][d]   * w;
        acc1 += xs[rq+4][d] * w;
    }
    h1[rq][a]   = tanhf(acc0);
    h1[rq+4][a] = tanhf(acc1);
    __syncthreads();
    if (tid < 64) {
        int rr = tid >> 3, r = tid & 7;
        float acc = b2[r];
        #pragma unroll 8
        for (int a2 = 0; a2 < DA; a2++)
            acc += h1[rr][a2] * w2[a2*R + r];
        g_s[(size_t)(row0+rr)*R + r] = acc;
    }
}

// ------- running softmax denominators: e = exp(s), iz = 1/cumsum(e) -------
__global__ void k_cumsum() {
    int tid = threadIdx.x;
    if (tid >= B*R) return;
    int b = tid >> 3, r = tid & 7;
    const float* sp = &g_s [(size_t)b*T*R + r];
    float*       ep = &g_e [(size_t)b*T*R + r];
    float*       zp = &g_iz[(size_t)b*T*R + r];
    float z = 0.f;
    #pragma unroll 4
    for (int t = 0; t < T; t++) {
        float e = expf(sp[t*R]);
        z += e;
        ep[t*R] = e;
        zp[t*R] = 1.0f / z;
    }
}

// ------- pass 1: per-chunk sums S[b,ch,r,d] = sum_{j in chunk} e[j,r]*x[j,d] -------
__global__ void k_M1(const float* __restrict__ x) {
    __shared__ float es[TC*R];
    int b = blockIdx.x >> 3, ch = blockIdx.x & 7;
    int tid = threadIdx.x;                 // 256
    int t0 = ch*TC;
    for (int i = tid; i < TC*R; i += 256)
        es[i] = g_e[((size_t)b*T + t0)*R + i];
    __syncthreads();
    int d = tid;
    float acc[R] = {};
    const float* xp = &x[((size_t)b*T + t0)*D + d];
    #pragma unroll 4
    for (int j = 0; j < TC; j++) {
        float xv = xp[(size_t)j*D];
        #pragma unroll
        for (int r = 0; r < R; r++) acc[r] += es[j*R + r] * xv;
    }
    float* sp = &g_S[((size_t)(b*NCH + ch)*R)*D + d];
    #pragma unroll
    for (int r = 0; r < R; r++) sp[r*D] = acc[r];
}

// ------- pass 2: within-chunk weighted cumsum, seeded by chunk prefix -------
__global__ void k_M2(const float* __restrict__ x) {
    __shared__ float4 es[TC*2];
    __shared__ float4 zs[TC*2];
    int bi = blockIdx.x;
    int b = bi >> 4, dh = (bi >> 3) & 1, ch = bi & 7;
    int tid = threadIdx.x;                 // 128
    int t0 = ch*TC;
    const float4* eg = (const float4*)&g_e [((size_t)b*T + t0)*R];
    const float4* zg = (const float4*)&g_iz[((size_t)b*T + t0)*R];
    for (int i = tid; i < TC*2; i += 128) { es[i] = eg[i]; zs[i] = zg[i]; }
    __syncthreads();
    int d = dh*128 + tid;
    float4 clo = {0,0,0,0}, chi = {0,0,0,0};
    for (int c = 0; c < ch; c++) {
        const float* sp = &g_S[((size_t)(b*NCH + c)*R)*D + d];
        clo.x += sp[0];   clo.y += sp[D];   clo.z += sp[2*D]; clo.w += sp[3*D];
        chi.x += sp[4*D]; chi.y += sp[5*D]; chi.z += sp[6*D]; chi.w += sp[7*D];
    }
    const float* xp = &x[((size_t)b*T + t0)*D + d];
    float*       mp = &g_M[((size_t)b*T + t0)*D + d];
    for (int j = 0; j < TC; j += 4) {
        float xv[4];
        #pragma unroll
        for (int u = 0; u < 4; u++) xv[u] = xp[(size_t)(j+u)*D];
        float mo[4];
        #pragma unroll
        for (int u = 0; u < 4; u++) {
            float4 ea = es[2*(j+u)], eb = es[2*(j+u)+1];
            clo.x += ea.x*xv[u]; clo.y += ea.y*xv[u]; clo.z += ea.z*xv[u]; clo.w += ea.w*xv[u];
            chi.x += eb.x*xv[u]; chi.y += eb.y*xv[u]; chi.z += eb.z*xv[u]; chi.w += eb.w*xv[u];
            float4 za = zs[2*(j+u)], zb = zs[2*(j+u)+1];
            mo[u] = (clo.x*za.x + clo.y*za.y + clo.z*za.z + clo.w*za.w
                   + chi.x*zb.x + chi.y*zb.y + chi.z*zb.z + chi.w*zb.w) * 0.125f;
        }
        #pragma unroll
        for (int u = 0; u < 4; u++) mp[(size_t)(j+u)*D] = mo[u];
    }
}

// ------- gates = M(8192x256) @ W_i(256x2048) + bias, 128x128x16 / 8x8 tiles -------
#define GBM 128
#define GBN 128
#define GBK 16
__global__ void __launch_bounds__(256)
k_gemm(const float* __restrict__ Wi, const float* __restrict__ bias) {
    __shared__ float As[GBK][GBM+4];
    __shared__ float Bs[GBK][GBN+4];
    int tid = threadIdx.x;             // 256
    int tx = tid & 15, ty = tid >> 4;
    int rb = blockIdx.y * GBM, nb = blockIdx.x * GBN;
    ull c2[8][4] = {};
    for (int kb = 0; kb < D; kb += GBK) {
        #pragma unroll
        for (int j = 0; j < 2; j++) {
            int lin = tid + j*256;
            int m = lin >> 2, kq = (lin & 3)*4;
            float4 v = *(const float4*)&g_M[(size_t)(rb+m)*D + kb + kq];
            As[kq+0][m] = v.x; As[kq+1][m] = v.y;
            As[kq+2][m] = v.z; As[kq+3][m] = v.w;
        }
        #pragma unroll
        for (int j = 0; j < 2; j++) {
            int lin = tid + j*256;
            int kk2 = lin >> 5, nq = (lin & 31)*4;
            *(float4*)&Bs[kk2][nq] = *(const float4*)&Wi[(size_t)(kb+kk2)*G4 + nb + nq];
        }
        __syncthreads();
        #pragma unroll
        for (int kk = 0; kk < GBK; kk++) {
            float4 a0 = *(const float4*)&As[kk][ty*8];
            float4 a1 = *(const float4*)&As[kk][ty*8+4];
            double2 b0 = *(const double2*)&Bs[kk][tx*8];
            double2 b1 = *(const double2*)&Bs[kk][tx*8+4];
            ull bx0 = dbl2u(b0.x), bx1 = dbl2u(b0.y);
            ull bx2 = dbl2u(b1.x), bx3 = dbl2u(b1.y);
            float av[8] = {a0.x,a0.y,a0.z,a0.w,a1.x,a1.y,a1.z,a1.w};
            #pragma unroll
            for (int i = 0; i < 8; i++) {
                ull ap = pack2(av[i]);
                ffma2(c2[i][0], ap, bx0); ffma2(c2[i][1], ap, bx1);
                ffma2(c2[i][2], ap, bx2); ffma2(c2[i][3], ap, bx3);
            }
        }
        __syncthreads();
    }
    float4 bv0 = *(const float4*)&bias[nb + tx*8];
    float4 bv1 = *(const float4*)&bias[nb + tx*8 + 4];
    #pragma unroll
    for (int i = 0; i < 8; i++) {
        int row = rb + ty*8 + i;
        float4 o0 = make_float4(lo2(c2[i][0])+bv0.x, hi2(c2[i][0])+bv0.y,
                                lo2(c2[i][1])+bv0.z, hi2(c2[i][1])+bv0.w);
        float4 o1 = make_float4(lo2(c2[i][2])+bv1.x, hi2(c2[i][2])+bv1.y,
                                lo2(c2[i][3])+bv1.z, hi2(c2[i][3])+bv1.w);
        *(float4*)&g_gates[(size_t)row*G4 + nb + tx*8]     = o0;
        *(float4*)&g_gates[(size_t)row*G4 + nb + tx*8 + 4] = o1;
    }
}

// ------- persistent LSTM scan v7 (R5 + L2-served H loads) -------
// Key fix vs R5: H staging used ld.global.cv which REFETCHES FROM DRAM
// (~577+ cyc on the serial critical path every step). Replaced with
// ld.volatile (L1-bypassing, L2-served ~234 cyc). h publishes are
// st.relaxed.gpu (strong). Fusion uses MUFU sigmoid/tanh and releases
// early via bar.sync 1,64 while other threads begin polling.
__global__ void __launch_bounds__(SCAN_THREADS, 1)
k_scan(const float* __restrict__ Whh, float* __restrict__ out) {
    extern __shared__ float sm[];
    float* Hs  = sm;                  // [512][16]  32 KB
    float* red = sm + 8192;           // [16 warps][16 c][20-pad b] 20 KB
    float* sg  = sm + 8192 + 5120;    // [16 c][16 b]
    int tid = threadIdx.x;
    int k = blockIdx.x;
    int lane = tid & 31, warp = tid >> 5;
    int cx = lane & 3, by = (lane>>2)&3, ksub = lane>>4;
    int kbase = warp*32 + ksub;            // thread covers h = kbase + 2*i, i<16
    int bb = tid >> 2, j2 = tid & 3;       // fusion mapping (tid<64)
    float creg = 0.f;

    // preload W slice into registers: wr[i] = Whh[kbase+2i][cx*HS + k*4 .. +3]
    float4 wr[16];
    #pragma unroll
    for (int i = 0; i < 16; i++)
        wr[i] = *(const float4*)&Whh[(size_t)(kbase + 2*i)*G4 + cx*HS + k*4];

    float* hid_out = out;                         // (B,T,HS)
    float* ht_out  = out + (size_t)B*T*HS;        // (B,HS)
    float* ct_out  = ht_out + B*HS;               // (B,HS)

    for (int t = 0; t < T; t++) {
        // prefetch gates_x for fusion threads (hidden under staging+dot)
        float gx0=0.f, gx1=0.f, gx2=0.f, gx3=0.f;
        if (tid < 64) {
            const float* gp = &g_gates[((size_t)bb*T + t)*G4 + k*4 + j2];
            gx0 = __ldg(gp); gx1 = __ldg(gp + HS);
            gx2 = __ldg(gp + 2*HS); gx3 = __ldg(gp + 3*HS);
        }

        // stage H into SMEM: 32 KB, coalesced, L1-bypassing, L2-SERVED
        {
            const float4* hb = (const float4*)&g_hbuf[t&1][0];
            float4* hs4 = (float4*)Hs;
            float4 v[4];
            #pragma unroll
            for (int j = 0; j < 4; j++) ldg_16_l2(&v[j], hb + tid + j*512);
            #pragma unroll
            for (int j = 0; j < 4; j++) hs4[tid + j*512] = v[j];
        }
        __syncthreads();

        // 4x4 outer-product dot over this thread's 32-h slice (W regs, H smem)
        ull acc[4][2] = {};
        #pragma unroll
        for (int i = 0; i < 16; i++) {
            double2 hd = *(const double2*)&Hs[(kbase + 2*i)*16 + by*4];
            ull hx = dbl2u(hd.x), hy = dbl2u(hd.y);
            ull w0 = pack2(wr[i].x), w1 = pack2(wr[i].y);
            ull w2 = pack2(wr[i].z), w3 = pack2(wr[i].w);
            ffma2(acc[0][0], w0, hx); ffma2(acc[0][1], w0, hy);
            ffma2(acc[1][0], w1, hx); ffma2(acc[1][1], w1, hy);
            ffma2(acc[2][0], w2, hx); ffma2(acc[2][1], w2, hy);
            ffma2(acc[3][0], w3, hx); ffma2(acc[3][1], w3, hy);
        }
        // reduce ksub pairs via shfl (lanes xor 16 share (cx,by))
        #pragma unroll
        for (int q = 0; q < 4; q++) {
            acc[q][0] = addf2(acc[q][0], __shfl_xor_sync(0xffffffffu, acc[q][0], 16));
            acc[q][1] = addf2(acc[q][1], __shfl_xor_sync(0xffffffffu, acc[q][1], 16));
        }
        if (ksub == 0) {
            float* rp = &red[warp*320 + (cx*4)*20 + by*4];
            #pragma unroll
            for (int q = 0; q < 4; q++) {
                float4 v = make_float4(lo2(acc[q][0]), hi2(acc[q][0]),
                                       lo2(acc[q][1]), hi2(acc[q][1]));
                *(float4*)(rp + q*20) = v;
            }
        }
        __syncthreads();

        // reduce 16 warps: thread tid<256 owns (c = tid>>4, b = tid&15)
        if (tid < 256) {
            int c = tid >> 4, b = tid & 15;
            float s0 = 0.f, s1 = 0.f;
            #pragma unroll
            for (int w = 0; w < 16; w += 2) {
                s0 += red[w*320 + c*20 + b];
                s1 += red[(w+1)*320 + c*20 + b];
            }
            sg[tid] = s0 + s1;
        }
        __syncthreads();

        // gate fusion (tid<64): MUFU activations, publish h strongly,
        // order within warps 0-1, then tid0 releases. Other threads are
        // already polling.
        if (tid < 64) {
            float gi = sg[( 0 + j2)*16 + bb] + gx0;
            float gf = sg[( 4 + j2)*16 + bb] + gx1;
            float gg = sg[( 8 + j2)*16 + bb] + gx2;
            float go = sg[(12 + j2)*16 + bb] + gx3;
            float iv = fsig(gi);
            float fv = fsig(gf);
            float gv = ftanh(gg);
            float ov = fsig(go);
            creg = fv*creg + iv*gv;
            float hv = ov * ftanh(creg);
            int hj = k*4 + j2;
            hid_out[((size_t)bb*T + t)*HS + hj] = hv;
            stg_rel_f32(&g_hbuf[(t+1)&1][hj*B + bb], hv);   // strong publish
            if (t == T-1) { ht_out[bb*HS + hj] = hv; ct_out[bb*HS + hj] = creg; }
            asm volatile("bar.sync 1, 64;" ::: "memory");
            if (tid == 0) st_release(&g_arrive[k*32], (unsigned)(t+1));
        }

        // grid barrier: per-CTA slots, acquire polls + nanosleep backoff
        if (tid < NCTA) {
            const unsigned* slot = &g_arrive[tid*32];
            while (ld_acquire(slot) < (unsigned)(t+1)) __nanosleep(20);
        }
        __syncthreads();   // gate next-step Hs overwrite on grid convergence
    }
}

extern "C" void kernel_launch(void* const* d_in, const int* in_sizes, int n_in,
                              void* d_out, int out_size) {
    const float* x    = (const float*)d_in[0];
    const float* w1   = (const float*)d_in[1];
    const float* b1   = (const float*)d_in[2];
    const float* w2   = (const float*)d_in[3];
    const float* b2   = (const float*)d_in[4];
    const float* Wi   = (const float*)d_in[5];
    const float* Whh  = (const float*)d_in[6];
    const float* bias = (const float*)d_in[7];
    float* out = (float*)d_out;

    (void)in_sizes; (void)n_in; (void)out_size;

    k_init<<<1, 256>>>();
    k_s<<<(B*T)/8, 256>>>(x, w1, b1, w2, b2);
    k_cumsum<<<1, 128>>>();
    k_M1<<<B*NCH, 256>>>(x);
    k_M2<<<B*2*NCH, 128>>>(x);
    dim3 gg(G4/GBN, (B*T)/GBM);
    k_gemm<<<gg, 256>>>(Wi, bias);

    size_t smem = (size_t)(8192 + 5120 + 256) * sizeof(float);   // 54,272 B
    cudaFuncSetAttribute(k_scan, cudaFuncAttributeMaxDynamicSharedMemorySize, (int)smem);
    k_scan<<<NCTA, SCAN_THREADS, smem>>>(Whh, out);
}